// round 8
// baseline (speedup 1.0000x reference)
#include <cuda_runtime.h>
#include <cuda_fp16.h>
#include <cstdint>

// ---------------------------------------------------------------------------
// Problem dims (fixed)
// ---------------------------------------------------------------------------
#define Bd 8
#define Sd 2048
#define Id 1024
#define Hd 4096
#define Od 1024
#define M_TOT (Bd * Sd)          // 16384

#define NCHUNK 16
#define CHUNK  128
#define NCH    (Bd * Id)         // 8192

// ---------------------------------------------------------------------------
// Scratch (__device__ globals, allocation-free)
// ---------------------------------------------------------------------------
__device__ __half g_xh[(size_t)M_TOT * Id];        // 32 MB
__device__ __half g_Wgh[(size_t)Id * Id];          //  2 MB
__device__ __half g_W1h[(size_t)Hd * Id];          //  8 MB
__device__ __half g_W2h[(size_t)Od * Hd];          //  8 MB
__device__ float  g_decay[(size_t)M_TOT * Id];     // 64 MB
__device__ __half g_comb[(size_t)M_TOT * Id];      // 32 MB
__device__ __half g_hidden[(size_t)M_TOT * Hd];    // 128 MB
__device__ float  g_P[NCHUNK * NCH];
__device__ float  g_Q[NCHUNK * NCH];

// ---------------------------------------------------------------------------
// PTX helpers
// ---------------------------------------------------------------------------
__device__ __forceinline__ uint32_t smem_u32(const void* p) {
    uint32_t a;
    asm("{ .reg .u64 t; cvta.to.shared.u64 t, %1; cvt.u32.u64 %0, t; }"
        : "=r"(a) : "l"(p));
    return a;
}

#define CP_ASYNC16(dst, src) \
    asm volatile("cp.async.cg.shared.global [%0], [%1], 16;" :: "r"(dst), "l"(src))
#define CP_COMMIT() asm volatile("cp.async.commit_group;" ::: "memory")
#define CP_WAIT(n)  asm volatile("cp.async.wait_group %0;" :: "n"(n) : "memory")

#define LDSM_X4(r0, r1, r2, r3, addr)                                        \
    asm volatile("ldmatrix.sync.aligned.m8n8.x4.shared.b16 {%0,%1,%2,%3}, [%4];" \
        : "=r"(r0), "=r"(r1), "=r"(r2), "=r"(r3) : "r"(addr))

__device__ __forceinline__ void mma16(float c[4], const uint32_t a[4], const uint32_t b[2]) {
    asm volatile(
        "mma.sync.aligned.m16n8k16.row.col.f32.f16.f16.f32 "
        "{%0,%1,%2,%3}, {%4,%5,%6,%7}, {%8,%9}, {%0,%1,%2,%3};"
        : "+f"(c[0]), "+f"(c[1]), "+f"(c[2]), "+f"(c[3])
        : "r"(a[0]), "r"(a[1]), "r"(a[2]), "r"(a[3]), "r"(b[0]), "r"(b[1]));
}

// ---------------------------------------------------------------------------
// fp16 GEMM: C[M,N] = act(A[M,K] @ B[N,K]^T + bias[N]); A,B fp16 K-contig.
// CTA tile 128x128, 4 warps (2x2 of 64x64 warp tiles), K-slab 64
// (128B fp16 rows), 3-stage cp.async multistage pipeline (fills issued
// BEFORE compute each stage -> ~2 slabs of prefetch slack), XOR-16B
// swizzle, ldmatrix.x4 fragment loads, fp32 accumulate.
// EPI: 0 = none (f32 out), 1 = relu (f16 out), 2 = sigmoid (f32 out)
// ---------------------------------------------------------------------------
#define KSLAB 64
#define ATILE 16384                   // 128 rows * 128 B
#define STAGE (2 * ATILE)             // A + B = 32 KB
#define NST 3
#define DYN_SMEM (NST * STAGE)        // 96 KB

__device__ __forceinline__ void fill_slab(uint32_t sbuf, const __half* ga,
                                          const __half* gb, int K, int k0, int tid) {
    const int r0 = tid >> 3;          // 0..15
    const int c  = tid & 7;           // 16B chunk within 128B row
#pragma unroll
    for (int q = 0; q < 8; q++) {
        const int row = r0 + q * 16;
        const uint32_t sw = (uint32_t)((c ^ (row & 7)) << 4);
        CP_ASYNC16(sbuf + row * 128 + sw, ga + (size_t)row * K + k0 + c * 8);
    }
#pragma unroll
    for (int q = 0; q < 8; q++) {
        const int row = r0 + q * 16;
        const uint32_t sw = (uint32_t)((c ^ (row & 7)) << 4);
        CP_ASYNC16(sbuf + ATILE + row * 128 + sw, gb + (size_t)row * K + k0 + c * 8);
    }
}

template <int EPI>
__global__ void __launch_bounds__(128, 2)
gemm_h(const __half* __restrict__ A, const __half* __restrict__ Bm,
       const float* __restrict__ bias, void* __restrict__ Cout,
       int M, int N, int K) {
    extern __shared__ char smem[];
    const uint32_t sb = smem_u32(smem);

    const int tid  = threadIdx.x;
    const int lane = tid & 31;
    const int warp = tid >> 5;
    const int g    = lane >> 2;
    const int tig  = lane & 3;
    const int wm   = (warp >> 1) * 64;
    const int wn   = (warp & 1) * 64;

    // ldmatrix lane->address mapping: A covers m16 x k16 tiles,
    // B covers n16 x k16 tiles (two mma B-frags per LDSM.x4).
    const int rA = wm + (lane & 15);
    const int cA = lane >> 4;                       // 0/1 -> k-half
    const int xA = rA & 7;
    const int rB = wn + (lane & 7) + ((lane >> 4) << 3);
    const int cB = (lane >> 3) & 1;
    const int xB = rB & 7;

    const size_t blockM = (size_t)blockIdx.y * 128;
    const size_t blockN = (size_t)blockIdx.x * 128;
    const __half* ga = A  + blockM * (size_t)K;
    const __half* gb = Bm + blockN * (size_t)K;

    float c[4][8][4] = {};

    const int nk = K / KSLAB;
    // prologue: slabs 0 and 1
    fill_slab(sb,         ga, gb, K, 0,     tid); CP_COMMIT();
    fill_slab(sb + STAGE, ga, gb, K, KSLAB, tid); CP_COMMIT();

    for (int kt = 0; kt < nk; kt++) {
        CP_WAIT(1);            // slab kt resident (commits: slabs 0..kt+1)
        __syncthreads();       // all warps done with slab kt-1's buffer

        // issue fill of slab kt+2 into buffer (kt+2)%NST (== (kt-1)%NST, free)
        if (kt + 2 < nk) {
            fill_slab(sb + ((kt + 2) % NST) * STAGE, ga, gb, K, (kt + 2) * KSLAB, tid);
        }
        CP_COMMIT();

        const uint32_t buf = sb + (kt % NST) * STAGE;
#pragma unroll
        for (int kk = 0; kk < 4; kk++) {            // 4 x k16 per slab
            uint32_t af[4][4], bf[8][2];
#pragma unroll
            for (int mt = 0; mt < 4; mt++) {
                const uint32_t addr = buf + (rA + mt * 16) * 128 +
                                      (uint32_t)(((kk * 2 + cA) ^ xA) << 4);
                LDSM_X4(af[mt][0], af[mt][1], af[mt][2], af[mt][3], addr);
            }
#pragma unroll
            for (int p = 0; p < 4; p++) {
                const uint32_t addr = buf + ATILE + (rB + p * 16) * 128 +
                                      (uint32_t)(((kk * 2 + cB) ^ xB) << 4);
                LDSM_X4(bf[2 * p][0], bf[2 * p][1], bf[2 * p + 1][0], bf[2 * p + 1][1], addr);
            }
#pragma unroll
            for (int mt = 0; mt < 4; mt++)
#pragma unroll
                for (int nt = 0; nt < 8; nt++)
                    mma16(c[mt][nt], af[mt], bf[nt]);
        }
    }

    // ---- epilogue ----
#pragma unroll
    for (int mt = 0; mt < 4; mt++) {
#pragma unroll
        for (int nt = 0; nt < 8; nt++) {
            const size_t row = blockM + wm + mt * 16 + g;
            const size_t col = blockN + wn + nt * 8 + 2 * tig;
            const float bv0 = __ldg(bias + col);
            const float bv1 = __ldg(bias + col + 1);
            float v00 = c[mt][nt][0] + bv0, v01 = c[mt][nt][1] + bv1;
            float v10 = c[mt][nt][2] + bv0, v11 = c[mt][nt][3] + bv1;
            if (EPI == 1) {
                v00 = v00 > 0.f ? v00 : 0.f;  v01 = v01 > 0.f ? v01 : 0.f;
                v10 = v10 > 0.f ? v10 : 0.f;  v11 = v11 > 0.f ? v11 : 0.f;
                __half* Ch = (__half*)Cout;
                *reinterpret_cast<__half2*>(&Ch[row * N + col]) =
                    __floats2half2_rn(v00, v01);
                *reinterpret_cast<__half2*>(&Ch[(row + 8) * N + col]) =
                    __floats2half2_rn(v10, v11);
            } else {
                if (EPI == 2) {
                    v00 = 1.f / (1.f + __expf(-v00)); v01 = 1.f / (1.f + __expf(-v01));
                    v10 = 1.f / (1.f + __expf(-v10)); v11 = 1.f / (1.f + __expf(-v11));
                }
                float* Cf = (float*)Cout;
                *reinterpret_cast<float2*>(&Cf[row * N + col]) = make_float2(v00, v01);
                *reinterpret_cast<float2*>(&Cf[(row + 8) * N + col]) = make_float2(v10, v11);
            }
        }
    }
}

// ---------------------------------------------------------------------------
// fp32 -> fp16 conversion (vectorized)
// ---------------------------------------------------------------------------
__global__ void f2h(const float* __restrict__ src, __half* __restrict__ dst, int n4) {
    const int i = blockIdx.x * blockDim.x + threadIdx.x;
    if (i < n4) {
        float4 v = reinterpret_cast<const float4*>(src)[i];
        __half2 h0 = __floats2half2_rn(v.x, v.y);
        __half2 h1 = __floats2half2_rn(v.z, v.w);
        uint2 u;
        u.x = *reinterpret_cast<uint32_t*>(&h0);
        u.y = *reinterpret_cast<uint32_t*>(&h1);
        reinterpret_cast<uint2*>(dst)[i] = u;
    }
}

// ---------------------------------------------------------------------------
// Recurrence (chunked linear scan); pass2 emits fp16 combined
// ---------------------------------------------------------------------------
__global__ void recur_pass1(const float* __restrict__ x) {
    const int idx   = blockIdx.x * blockDim.x + threadIdx.x;
    const int ch    = idx & (NCH - 1);
    const int chunk = idx >> 13;
    const int b     = ch >> 10;
    const int i     = ch & (Id - 1);
    size_t base = (size_t)b * Sd * Id + (size_t)chunk * CHUNK * Id + i;

    float P = 1.f, Q = 0.f;
#pragma unroll 8
    for (int t = 0; t < CHUNK; t++) {
        const float d  = g_decay[base + (size_t)t * Id];
        const float xv = x[base + (size_t)t * Id];
        P *= d;
        Q = Q * d + (1.f - d) * xv;
    }
    g_P[chunk * NCH + ch] = P;
    g_Q[chunk * NCH + ch] = Q;
}

__global__ void recur_pass2(const float* __restrict__ x) {
    const int idx   = blockIdx.x * blockDim.x + threadIdx.x;
    const int ch    = idx & (NCH - 1);
    const int chunk = idx >> 13;
    const int b     = ch >> 10;
    const int i     = ch & (Id - 1);
    size_t base = (size_t)b * Sd * Id + (size_t)chunk * CHUNK * Id + i;

    float buf = 0.f;
    for (int j = 0; j < chunk; j++)
        buf = g_P[j * NCH + ch] * buf + g_Q[j * NCH + ch];

#pragma unroll 8
    for (int t = 0; t < CHUNK; t++) {
        const float d  = g_decay[base + (size_t)t * Id];
        const float xv = x[base + (size_t)t * Id];
        buf = buf * d + (1.f - d) * xv;
        g_comb[base + (size_t)t * Id] = __float2half_rn(xv * d + buf);
    }
}

// ---------------------------------------------------------------------------
// Launch
// ---------------------------------------------------------------------------
extern "C" void kernel_launch(void* const* d_in, const int* in_sizes, int n_in,
                              void* d_out, int out_size) {
    const float* x  = (const float*)d_in[0];
    const float* W1 = (const float*)d_in[1];
    const float* b1 = (const float*)d_in[2];
    const float* W2 = (const float*)d_in[3];
    const float* b2 = (const float*)d_in[4];
    const float* Wg = (const float*)d_in[5];
    const float* bg = (const float*)d_in[6];

    __half *xh, *Wgh, *W1h, *W2h, *comb, *hidden;
    float *decay;
    cudaGetSymbolAddress((void**)&xh, g_xh);
    cudaGetSymbolAddress((void**)&Wgh, g_Wgh);
    cudaGetSymbolAddress((void**)&W1h, g_W1h);
    cudaGetSymbolAddress((void**)&W2h, g_W2h);
    cudaGetSymbolAddress((void**)&decay, g_decay);
    cudaGetSymbolAddress((void**)&comb, g_comb);
    cudaGetSymbolAddress((void**)&hidden, g_hidden);

    cudaFuncSetAttribute(gemm_h<0>, cudaFuncAttributeMaxDynamicSharedMemorySize, DYN_SMEM);
    cudaFuncSetAttribute(gemm_h<1>, cudaFuncAttributeMaxDynamicSharedMemorySize, DYN_SMEM);
    cudaFuncSetAttribute(gemm_h<2>, cudaFuncAttributeMaxDynamicSharedMemorySize, DYN_SMEM);

    // 0) fp16 copies of MMA operand inputs
    f2h<<<(M_TOT * Id / 4) / 256, 256>>>(x, xh, M_TOT * Id / 4);
    f2h<<<(Id * Id / 4) / 256, 256>>>(Wg, Wgh, Id * Id / 4);
    f2h<<<(Hd * Id / 4) / 256, 256>>>(W1, W1h, Hd * Id / 4);
    f2h<<<(Od * Hd / 4) / 256, 256>>>(W2, W2h, Od * Hd / 4);

    // 1) decay = sigmoid(x @ Wg^T + bg)
    gemm_h<2><<<dim3(Id / 128, M_TOT / 128), 128, DYN_SMEM>>>(
        xh, Wgh, bg, decay, M_TOT, Id, Id);
    // 2) recurrence -> combined (fp16)
    recur_pass1<<<(NCHUNK * NCH) / 256, 256>>>(x);
    recur_pass2<<<(NCHUNK * NCH) / 256, 256>>>(x);
    // 3) hidden = relu(combined @ W1^T + b1) -> fp16
    gemm_h<1><<<dim3(Hd / 128, M_TOT / 128), 128, DYN_SMEM>>>(
        comb, W1h, b1, hidden, M_TOT, Hd, Id);
    // 4) out = hidden @ W2^T + b2 -> fp32
    gemm_h<0><<<dim3(Od / 128, M_TOT / 128), 128, DYN_SMEM>>>(
        hidden, W2h, b2, d_out, M_TOT, Od, Hd);
}

// round 10
// speedup vs baseline: 1.4994x; 1.4994x over previous
#include <cuda_runtime.h>
#include <cuda_fp16.h>
#include <cstdint>

// ---------------------------------------------------------------------------
// Problem dims (fixed)
// ---------------------------------------------------------------------------
#define Bd 8
#define Sd 2048
#define Id 1024
#define Hd 4096
#define Od 1024
#define M_TOT (Bd * Sd)          // 16384

#define NCHUNK 16
#define CHUNK  128
#define NCH    (Bd * Id)         // 8192

// ---------------------------------------------------------------------------
// Scratch (__device__ globals, allocation-free)
// ---------------------------------------------------------------------------
__device__ __half g_xh[(size_t)M_TOT * Id];        // 32 MB
__device__ __half g_Wgh[(size_t)Id * Id];          //  2 MB
__device__ __half g_W1h[(size_t)Hd * Id];          //  8 MB
__device__ __half g_W2h[(size_t)Od * Hd];          //  8 MB
__device__ float  g_decay[(size_t)M_TOT * Id];     // 64 MB
__device__ __half g_comb[(size_t)M_TOT * Id];      // 32 MB
__device__ __half g_hidden[(size_t)M_TOT * Hd];    // 128 MB
__device__ float  g_P[NCHUNK * NCH];
__device__ float  g_Q[NCHUNK * NCH];

// ---------------------------------------------------------------------------
// PTX helpers
// ---------------------------------------------------------------------------
__device__ __forceinline__ uint32_t smem_u32(const void* p) {
    uint32_t a;
    asm("{ .reg .u64 t; cvta.to.shared.u64 t, %1; cvt.u32.u64 %0, t; }"
        : "=r"(a) : "l"(p));
    return a;
}

#define CP_ASYNC16(dst, src) \
    asm volatile("cp.async.cg.shared.global [%0], [%1], 16;" :: "r"(dst), "l"(src))
#define CP_COMMIT() asm volatile("cp.async.commit_group;" ::: "memory")
#define CP_WAIT(n)  asm volatile("cp.async.wait_group %0;" :: "n"(n) : "memory")

#define LDSM_X4(r0, r1, r2, r3, addr)                                        \
    asm volatile("ldmatrix.sync.aligned.m8n8.x4.shared.b16 {%0,%1,%2,%3}, [%4];" \
        : "=r"(r0), "=r"(r1), "=r"(r2), "=r"(r3) : "r"(addr))

__device__ __forceinline__ void mma16(float c[4], const uint32_t a[4], const uint32_t b[2]) {
    asm volatile(
        "mma.sync.aligned.m16n8k16.row.col.f32.f16.f16.f32 "
        "{%0,%1,%2,%3}, {%4,%5,%6,%7}, {%8,%9}, {%0,%1,%2,%3};"
        : "+f"(c[0]), "+f"(c[1]), "+f"(c[2]), "+f"(c[3])
        : "r"(a[0]), "r"(a[1]), "r"(a[2]), "r"(a[3]), "r"(b[0]), "r"(b[1]));
}

// ---------------------------------------------------------------------------
// fp16 GEMM: C[M,N] = act(A[M,K] @ B[N,K]^T + bias[N]); A,B fp16 K-contig.
// CTA tile 128x128, 4 warps (2x2 of 64x64 warp tiles), K-slab 64
// (128B fp16 rows), 2-stage cp.async pipeline (64 KB smem, 2 CTAs/SM).
// Two latency optimizations vs the plain 2-stage version:
//  (a) fragment double-buffering across kk (LDSM for kk+1 overlaps mma kk)
//  (b) the fill for slab kt+2 is issued right after the LAST smem reads of
//      slab kt (post-sync), into the same buffer, BEFORE kk=3's mmas ->
//      ~1.25 slabs of cp.async slack despite only 2 stages.
// EPI: 0 = none (f32 out), 1 = relu (f16 out), 2 = sigmoid (f32 out)
// ---------------------------------------------------------------------------
#define KSLAB 64
#define ATILE 16384                   // 128 rows * 128 B
#define STAGE (2 * ATILE)             // A + B = 32 KB
#define DYN_SMEM (2 * STAGE)          // 64 KB

__device__ __forceinline__ void fill_slab(uint32_t sbuf, const __half* ga,
                                          const __half* gb, int K, int k0, int tid) {
    const int r0 = tid >> 3;          // 0..15
    const int c  = tid & 7;           // 16B chunk within 128B row
#pragma unroll
    for (int q = 0; q < 8; q++) {
        const int row = r0 + q * 16;
        const uint32_t sw = (uint32_t)((c ^ (row & 7)) << 4);
        CP_ASYNC16(sbuf + row * 128 + sw, ga + (size_t)row * K + k0 + c * 8);
    }
#pragma unroll
    for (int q = 0; q < 8; q++) {
        const int row = r0 + q * 16;
        const uint32_t sw = (uint32_t)((c ^ (row & 7)) << 4);
        CP_ASYNC16(sbuf + ATILE + row * 128 + sw, gb + (size_t)row * K + k0 + c * 8);
    }
}

struct FragCoords {
    int rA, cA, xA, rB, cB, xB;
};

__device__ __forceinline__ void load_frags(uint32_t buf, int kk,
                                           uint32_t af[4][4], uint32_t bf[8][2],
                                           const FragCoords& fc) {
#pragma unroll
    for (int mt = 0; mt < 4; mt++) {
        const uint32_t addr = buf + (fc.rA + mt * 16) * 128 +
                              (uint32_t)(((kk * 2 + fc.cA) ^ fc.xA) << 4);
        LDSM_X4(af[mt][0], af[mt][1], af[mt][2], af[mt][3], addr);
    }
#pragma unroll
    for (int p = 0; p < 4; p++) {
        const uint32_t addr = buf + ATILE + (fc.rB + p * 16) * 128 +
                              (uint32_t)(((kk * 2 + fc.cB) ^ fc.xB) << 4);
        LDSM_X4(bf[2 * p][0], bf[2 * p][1], bf[2 * p + 1][0], bf[2 * p + 1][1], addr);
    }
}

template <int EPI>
__global__ void __launch_bounds__(128, 2)
gemm_h(const __half* __restrict__ A, const __half* __restrict__ Bm,
       const float* __restrict__ bias, void* __restrict__ Cout,
       int M, int N, int K) {
    extern __shared__ char smem[];
    const uint32_t sb = smem_u32(smem);

    const int tid  = threadIdx.x;
    const int lane = tid & 31;
    const int warp = tid >> 5;
    const int g    = lane >> 2;
    const int tig  = lane & 3;
    const int wm   = (warp >> 1) * 64;
    const int wn   = (warp & 1) * 64;

    FragCoords fc;
    fc.rA = wm + (lane & 15);
    fc.cA = lane >> 4;                       // 0/1 -> k-half
    fc.xA = fc.rA & 7;
    fc.rB = wn + (lane & 7) + ((lane >> 4) << 3);
    fc.cB = (lane >> 3) & 1;
    fc.xB = fc.rB & 7;

    const size_t blockM = (size_t)blockIdx.y * 128;
    const size_t blockN = (size_t)blockIdx.x * 128;
    const __half* ga = A  + blockM * (size_t)K;
    const __half* gb = Bm + blockN * (size_t)K;

    float c[4][8][4] = {};

    const int nk = K / KSLAB;
    fill_slab(sb,         ga, gb, K, 0,     tid); CP_COMMIT();
    fill_slab(sb + STAGE, ga, gb, K, KSLAB, tid); CP_COMMIT();

    for (int kt = 0; kt < nk; kt++) {
        CP_WAIT(1);            // slab kt resident
        __syncthreads();       // cross-thread visibility of slab kt

        const uint32_t buf = sb + (kt & 1) * STAGE;
        uint32_t af[2][4][4], bf[2][8][2];
        load_frags(buf, 0, af[0], bf[0], fc);

#pragma unroll
        for (int kk = 0; kk < 4; kk++) {
            const int cur = kk & 1;
            if (kk < 3) {
                // prefetch next k16 fragments while computing current ones
                load_frags(buf, kk + 1, af[cur ^ 1], bf[cur ^ 1], fc);
            } else {
                // all smem reads for this slab are now in registers:
                // hand the buffer to the next fill before the last mmas
                __syncthreads();
                if (kt + 2 < nk)
                    fill_slab(buf, ga, gb, K, (kt + 2) * KSLAB, tid);
                CP_COMMIT();
            }
#pragma unroll
            for (int mt = 0; mt < 4; mt++)
#pragma unroll
                for (int nt = 0; nt < 8; nt++)
                    mma16(c[mt][nt], af[cur][mt], bf[cur][nt]);
        }
    }

    // ---- epilogue ----
#pragma unroll
    for (int mt = 0; mt < 4; mt++) {
#pragma unroll
        for (int nt = 0; nt < 8; nt++) {
            const size_t row = blockM + wm + mt * 16 + g;
            const size_t col = blockN + wn + nt * 8 + 2 * tig;
            const float bv0 = __ldg(bias + col);
            const float bv1 = __ldg(bias + col + 1);
            float v00 = c[mt][nt][0] + bv0, v01 = c[mt][nt][1] + bv1;
            float v10 = c[mt][nt][2] + bv0, v11 = c[mt][nt][3] + bv1;
            if (EPI == 1) {
                v00 = v00 > 0.f ? v00 : 0.f;  v01 = v01 > 0.f ? v01 : 0.f;
                v10 = v10 > 0.f ? v10 : 0.f;  v11 = v11 > 0.f ? v11 : 0.f;
                __half* Ch = (__half*)Cout;
                *reinterpret_cast<__half2*>(&Ch[row * N + col]) =
                    __floats2half2_rn(v00, v01);
                *reinterpret_cast<__half2*>(&Ch[(row + 8) * N + col]) =
                    __floats2half2_rn(v10, v11);
            } else {
                if (EPI == 2) {
                    v00 = 1.f / (1.f + __expf(-v00)); v01 = 1.f / (1.f + __expf(-v01));
                    v10 = 1.f / (1.f + __expf(-v10)); v11 = 1.f / (1.f + __expf(-v11));
                }
                float* Cf = (float*)Cout;
                *reinterpret_cast<float2*>(&Cf[row * N + col]) = make_float2(v00, v01);
                *reinterpret_cast<float2*>(&Cf[(row + 8) * N + col]) = make_float2(v10, v11);
            }
        }
    }
}

// ---------------------------------------------------------------------------
// fp32 -> fp16 conversion (vectorized)  [clock canary: ~7us fast state]
// ---------------------------------------------------------------------------
__global__ void f2h(const float* __restrict__ src, __half* __restrict__ dst, int n4) {
    const int i = blockIdx.x * blockDim.x + threadIdx.x;
    if (i < n4) {
        float4 v = reinterpret_cast<const float4*>(src)[i];
        __half2 h0 = __floats2half2_rn(v.x, v.y);
        __half2 h1 = __floats2half2_rn(v.z, v.w);
        uint2 u;
        u.x = *reinterpret_cast<uint32_t*>(&h0);
        u.y = *reinterpret_cast<uint32_t*>(&h1);
        reinterpret_cast<uint2*>(dst)[i] = u;
    }
}

// ---------------------------------------------------------------------------
// Recurrence (chunked linear scan); pass2 emits fp16 combined
// ---------------------------------------------------------------------------
__global__ void recur_pass1(const float* __restrict__ x) {
    const int idx   = blockIdx.x * blockDim.x + threadIdx.x;
    const int ch    = idx & (NCH - 1);
    const int chunk = idx >> 13;
    const int b     = ch >> 10;
    const int i     = ch & (Id - 1);
    size_t base = (size_t)b * Sd * Id + (size_t)chunk * CHUNK * Id + i;

    float P = 1.f, Q = 0.f;
#pragma unroll 8
    for (int t = 0; t < CHUNK; t++) {
        const float d  = g_decay[base + (size_t)t * Id];
        const float xv = x[base + (size_t)t * Id];
        P *= d;
        Q = Q * d + (1.f - d) * xv;
    }
    g_P[chunk * NCH + ch] = P;
    g_Q[chunk * NCH + ch] = Q;
}

__global__ void recur_pass2(const float* __restrict__ x) {
    const int idx   = blockIdx.x * blockDim.x + threadIdx.x;
    const int ch    = idx & (NCH - 1);
    const int chunk = idx >> 13;
    const int b     = ch >> 10;
    const int i     = ch & (Id - 1);
    size_t base = (size_t)b * Sd * Id + (size_t)chunk * CHUNK * Id + i;

    float buf = 0.f;
    for (int j = 0; j < chunk; j++)
        buf = g_P[j * NCH + ch] * buf + g_Q[j * NCH + ch];

#pragma unroll 8
    for (int t = 0; t < CHUNK; t++) {
        const float d  = g_decay[base + (size_t)t * Id];
        const float xv = x[base + (size_t)t * Id];
        buf = buf * d + (1.f - d) * xv;
        g_comb[base + (size_t)t * Id] = __float2half_rn(xv * d + buf);
    }
}

// ---------------------------------------------------------------------------
// Launch
// ---------------------------------------------------------------------------
extern "C" void kernel_launch(void* const* d_in, const int* in_sizes, int n_in,
                              void* d_out, int out_size) {
    const float* x  = (const float*)d_in[0];
    const float* W1 = (const float*)d_in[1];
    const float* b1 = (const float*)d_in[2];
    const float* W2 = (const float*)d_in[3];
    const float* b2 = (const float*)d_in[4];
    const float* Wg = (const float*)d_in[5];
    const float* bg = (const float*)d_in[6];

    __half *xh, *Wgh, *W1h, *W2h, *comb, *hidden;
    float *decay;
    cudaGetSymbolAddress((void**)&xh, g_xh);
    cudaGetSymbolAddress((void**)&Wgh, g_Wgh);
    cudaGetSymbolAddress((void**)&W1h, g_W1h);
    cudaGetSymbolAddress((void**)&W2h, g_W2h);
    cudaGetSymbolAddress((void**)&decay, g_decay);
    cudaGetSymbolAddress((void**)&comb, g_comb);
    cudaGetSymbolAddress((void**)&hidden, g_hidden);

    cudaFuncSetAttribute(gemm_h<0>, cudaFuncAttributeMaxDynamicSharedMemorySize, DYN_SMEM);
    cudaFuncSetAttribute(gemm_h<1>, cudaFuncAttributeMaxDynamicSharedMemorySize, DYN_SMEM);
    cudaFuncSetAttribute(gemm_h<2>, cudaFuncAttributeMaxDynamicSharedMemorySize, DYN_SMEM);

    // 0) fp16 copies of MMA operand inputs
    f2h<<<(M_TOT * Id / 4) / 256, 256>>>(x, xh, M_TOT * Id / 4);
    f2h<<<(Id * Id / 4) / 256, 256>>>(Wg, Wgh, Id * Id / 4);
    f2h<<<(Hd * Id / 4) / 256, 256>>>(W1, W1h, Hd * Id / 4);
    f2h<<<(Od * Hd / 4) / 256, 256>>>(W2, W2h, Od * Hd / 4);

    // 1) decay = sigmoid(x @ Wg^T + bg)
    gemm_h<2><<<dim3(Id / 128, M_TOT / 128), 128, DYN_SMEM>>>(
        xh, Wgh, bg, decay, M_TOT, Id, Id);
    // 2) recurrence -> combined (fp16)
    recur_pass1<<<(NCHUNK * NCH) / 256, 256>>>(x);
    recur_pass2<<<(NCHUNK * NCH) / 256, 256>>>(x);
    // 3) hidden = relu(combined @ W1^T + b1) -> fp16
    gemm_h<1><<<dim3(Hd / 128, M_TOT / 128), 128, DYN_SMEM>>>(
        comb, W1h, b1, hidden, M_TOT, Hd, Id);
    // 4) out = hidden @ W2^T + b2 -> fp32
    gemm_h<0><<<dim3(Od / 128, M_TOT / 128), 128, DYN_SMEM>>>(
        hidden, W2h, b2, d_out, M_TOT, Od, Hd);
}

// round 11
// speedup vs baseline: 1.5212x; 1.0145x over previous
#include <cuda_runtime.h>
#include <cuda_fp16.h>
#include <cstdint>

// ---------------------------------------------------------------------------
// Problem dims (fixed)
// ---------------------------------------------------------------------------
#define Bd 8
#define Sd 2048
#define Id 1024
#define Hd 4096
#define Od 1024
#define M_TOT (Bd * Sd)          // 16384

#define NCHUNK 16
#define CHUNK  128
#define NCH    (Bd * Id)         // 8192

// ---------------------------------------------------------------------------
// Scratch (__device__ globals, allocation-free)
// ---------------------------------------------------------------------------
__device__ __half g_xh[(size_t)M_TOT * Id];        // 32 MB
__device__ __half g_Wgh[(size_t)Id * Id];          //  2 MB
__device__ __half g_W1h[(size_t)Hd * Id];          //  8 MB
__device__ __half g_W2h[(size_t)Od * Hd];          //  8 MB
__device__ float  g_decay[(size_t)M_TOT * Id];     // 64 MB
__device__ __half g_comb[(size_t)M_TOT * Id];      // 32 MB
__device__ __half g_hidden[(size_t)M_TOT * Hd];    // 128 MB
__device__ float  g_P[NCHUNK * NCH];
__device__ float  g_Q[NCHUNK * NCH];

// ---------------------------------------------------------------------------
// PTX helpers
// ---------------------------------------------------------------------------
__device__ __forceinline__ uint32_t smem_u32(const void* p) {
    uint32_t a;
    asm("{ .reg .u64 t; cvta.to.shared.u64 t, %1; cvt.u32.u64 %0, t; }"
        : "=r"(a) : "l"(p));
    return a;
}

#define CP_ASYNC16(dst, src) \
    asm volatile("cp.async.cg.shared.global [%0], [%1], 16;" :: "r"(dst), "l"(src))
#define CP_COMMIT() asm volatile("cp.async.commit_group;" ::: "memory")
#define CP_WAIT(n)  asm volatile("cp.async.wait_group %0;" :: "n"(n) : "memory")

#define LDSM_X4(r0, r1, r2, r3, addr)                                        \
    asm volatile("ldmatrix.sync.aligned.m8n8.x4.shared.b16 {%0,%1,%2,%3}, [%4];" \
        : "=r"(r0), "=r"(r1), "=r"(r2), "=r"(r3) : "r"(addr))

__device__ __forceinline__ void mma16(float c[4], const uint32_t a[4], const uint32_t b[2]) {
    asm volatile(
        "mma.sync.aligned.m16n8k16.row.col.f32.f16.f16.f32 "
        "{%0,%1,%2,%3}, {%4,%5,%6,%7}, {%8,%9}, {%0,%1,%2,%3};"
        : "+f"(c[0]), "+f"(c[1]), "+f"(c[2]), "+f"(c[3])
        : "r"(a[0]), "r"(a[1]), "r"(a[2]), "r"(a[3]), "r"(b[0]), "r"(b[1]));
}

// ---------------------------------------------------------------------------
// fp16 GEMM: C[M,N] = act(A[M,K] @ B[N,K]^T + bias[N]); A,B fp16 K-contig.
// CTA tile 128x128, 4 warps (2x2 of 64x64 warp tiles), K-slab 64
// (128B fp16 rows), 2-stage cp.async pipeline (64 KB smem, 2 CTAs/SM).
//  (a) fragment double-buffering across kk (LDSM for kk+1 overlaps mma kk)
//  (b) fill for slab kt+2 issued right after the LAST smem reads of slab kt
//      (post-sync), into the same buffer, BEFORE kk=3's mmas.
// EPI: 0 = none (f32 out), 1 = relu (f16 out), 2 = sigmoid (f32 out)
// ---------------------------------------------------------------------------
#define KSLAB 64
#define ATILE 16384                   // 128 rows * 128 B
#define STAGE (2 * ATILE)             // A + B = 32 KB
#define DYN_SMEM (2 * STAGE)          // 64 KB

__device__ __forceinline__ void fill_slab(uint32_t sbuf, const __half* ga,
                                          const __half* gb, int K, int k0, int tid) {
    const int r0 = tid >> 3;          // 0..15
    const int c  = tid & 7;           // 16B chunk within 128B row
#pragma unroll
    for (int q = 0; q < 8; q++) {
        const int row = r0 + q * 16;
        const uint32_t sw = (uint32_t)((c ^ (row & 7)) << 4);
        CP_ASYNC16(sbuf + row * 128 + sw, ga + (size_t)row * K + k0 + c * 8);
    }
#pragma unroll
    for (int q = 0; q < 8; q++) {
        const int row = r0 + q * 16;
        const uint32_t sw = (uint32_t)((c ^ (row & 7)) << 4);
        CP_ASYNC16(sbuf + ATILE + row * 128 + sw, gb + (size_t)row * K + k0 + c * 8);
    }
}

struct FragCoords {
    int rA, cA, xA, rB, cB, xB;
};

__device__ __forceinline__ void load_frags(uint32_t buf, int kk,
                                           uint32_t af[4][4], uint32_t bf[8][2],
                                           const FragCoords& fc) {
#pragma unroll
    for (int mt = 0; mt < 4; mt++) {
        const uint32_t addr = buf + (fc.rA + mt * 16) * 128 +
                              (uint32_t)(((kk * 2 + fc.cA) ^ fc.xA) << 4);
        LDSM_X4(af[mt][0], af[mt][1], af[mt][2], af[mt][3], addr);
    }
#pragma unroll
    for (int p = 0; p < 4; p++) {
        const uint32_t addr = buf + ATILE + (fc.rB + p * 16) * 128 +
                              (uint32_t)(((kk * 2 + fc.cB) ^ fc.xB) << 4);
        LDSM_X4(bf[2 * p][0], bf[2 * p][1], bf[2 * p + 1][0], bf[2 * p + 1][1], addr);
    }
}

template <int EPI>
__global__ void __launch_bounds__(128, 2)
gemm_h(const __half* __restrict__ A, const __half* __restrict__ Bm,
       const float* __restrict__ bias, void* __restrict__ Cout,
       int M, int N, int K) {
    extern __shared__ char smem[];
    const uint32_t sb = smem_u32(smem);

    const int tid  = threadIdx.x;
    const int lane = tid & 31;
    const int warp = tid >> 5;
    const int g    = lane >> 2;
    const int tig  = lane & 3;
    const int wm   = (warp >> 1) * 64;
    const int wn   = (warp & 1) * 64;

    FragCoords fc;
    fc.rA = wm + (lane & 15);
    fc.cA = lane >> 4;                       // 0/1 -> k-half
    fc.xA = fc.rA & 7;
    fc.rB = wn + (lane & 7) + ((lane >> 4) << 3);
    fc.cB = (lane >> 3) & 1;
    fc.xB = fc.rB & 7;

    const size_t blockM = (size_t)blockIdx.y * 128;
    const size_t blockN = (size_t)blockIdx.x * 128;
    const __half* ga = A  + blockM * (size_t)K;
    const __half* gb = Bm + blockN * (size_t)K;

    float c[4][8][4] = {};

    const int nk = K / KSLAB;
    fill_slab(sb,         ga, gb, K, 0,     tid); CP_COMMIT();
    fill_slab(sb + STAGE, ga, gb, K, KSLAB, tid); CP_COMMIT();

    for (int kt = 0; kt < nk; kt++) {
        CP_WAIT(1);            // slab kt resident
        __syncthreads();       // cross-thread visibility of slab kt

        const uint32_t buf = sb + (kt & 1) * STAGE;
        uint32_t af[2][4][4], bf[2][8][2];
        load_frags(buf, 0, af[0], bf[0], fc);

#pragma unroll
        for (int kk = 0; kk < 4; kk++) {
            const int cur = kk & 1;
            if (kk < 3) {
                // prefetch next k16 fragments while computing current ones
                load_frags(buf, kk + 1, af[cur ^ 1], bf[cur ^ 1], fc);
            } else {
                // all smem reads for this slab are now in registers:
                // hand the buffer to the next fill before the last mmas
                __syncthreads();
                if (kt + 2 < nk)
                    fill_slab(buf, ga, gb, K, (kt + 2) * KSLAB, tid);
                CP_COMMIT();
            }
#pragma unroll
            for (int mt = 0; mt < 4; mt++)
#pragma unroll
                for (int nt = 0; nt < 8; nt++)
                    mma16(c[mt][nt], af[cur][mt], bf[cur][nt]);
        }
    }

    // ---- epilogue ----
#pragma unroll
    for (int mt = 0; mt < 4; mt++) {
#pragma unroll
        for (int nt = 0; nt < 8; nt++) {
            const size_t row = blockM + wm + mt * 16 + g;
            const size_t col = blockN + wn + nt * 8 + 2 * tig;
            const float bv0 = __ldg(bias + col);
            const float bv1 = __ldg(bias + col + 1);
            float v00 = c[mt][nt][0] + bv0, v01 = c[mt][nt][1] + bv1;
            float v10 = c[mt][nt][2] + bv0, v11 = c[mt][nt][3] + bv1;
            if (EPI == 1) {
                v00 = v00 > 0.f ? v00 : 0.f;  v01 = v01 > 0.f ? v01 : 0.f;
                v10 = v10 > 0.f ? v10 : 0.f;  v11 = v11 > 0.f ? v11 : 0.f;
                __half* Ch = (__half*)Cout;
                *reinterpret_cast<__half2*>(&Ch[row * N + col]) =
                    __floats2half2_rn(v00, v01);
                *reinterpret_cast<__half2*>(&Ch[(row + 8) * N + col]) =
                    __floats2half2_rn(v10, v11);
            } else {
                if (EPI == 2) {
                    v00 = 1.f / (1.f + __expf(-v00)); v01 = 1.f / (1.f + __expf(-v01));
                    v10 = 1.f / (1.f + __expf(-v10)); v11 = 1.f / (1.f + __expf(-v11));
                }
                float* Cf = (float*)Cout;
                *reinterpret_cast<float2*>(&Cf[row * N + col]) = make_float2(v00, v01);
                *reinterpret_cast<float2*>(&Cf[(row + 8) * N + col]) = make_float2(v10, v11);
            }
        }
    }
}

// ---------------------------------------------------------------------------
// Merged fp32 -> fp16 conversion for x, W1, W2, Wg (single launch; also the
// clock canary). Ranges in float4 units:
//   x  : [0, 4194304)      W1 : [4194304, 5242880)
//   W2 : [5242880, 6291456) Wg : [6291456, 6553600)
// ---------------------------------------------------------------------------
#define F2H_N4_X  4194304
#define F2H_N4_W1 1048576
#define F2H_N4_W2 1048576
#define F2H_N4_WG 262144
#define F2H_TOTAL (F2H_N4_X + F2H_N4_W1 + F2H_N4_W2 + F2H_N4_WG)  // 6553600

__global__ void f2hall(const float* __restrict__ x,  const float* __restrict__ W1,
                       const float* __restrict__ W2, const float* __restrict__ Wg,
                       __half* __restrict__ xh,  __half* __restrict__ W1h,
                       __half* __restrict__ W2h, __half* __restrict__ Wgh) {
    int i = blockIdx.x * blockDim.x + threadIdx.x;
    const float* src;
    __half* dst;
    if (i < F2H_N4_X)                      { src = x;  dst = xh; }
    else if (i < F2H_N4_X + F2H_N4_W1)     { src = W1; dst = W1h; i -= F2H_N4_X; }
    else if (i < F2H_N4_X + F2H_N4_W1 + F2H_N4_W2)
                                           { src = W2; dst = W2h; i -= F2H_N4_X + F2H_N4_W1; }
    else                                   { src = Wg; dst = Wgh; i -= F2H_N4_X + F2H_N4_W1 + F2H_N4_W2; }
    float4 v = reinterpret_cast<const float4*>(src)[i];
    __half2 h0 = __floats2half2_rn(v.x, v.y);
    __half2 h1 = __floats2half2_rn(v.z, v.w);
    uint2 u;
    u.x = *reinterpret_cast<uint32_t*>(&h0);
    u.y = *reinterpret_cast<uint32_t*>(&h1);
    reinterpret_cast<uint2*>(dst)[i] = u;
}

// ---------------------------------------------------------------------------
// Recurrence (chunked linear scan); reads fp16 x, writes fp16 combined
// ---------------------------------------------------------------------------
__global__ void recur_pass1(const __half* __restrict__ xh) {
    const int idx   = blockIdx.x * blockDim.x + threadIdx.x;
    const int ch    = idx & (NCH - 1);
    const int chunk = idx >> 13;
    const int b     = ch >> 10;
    const int i     = ch & (Id - 1);
    size_t base = (size_t)b * Sd * Id + (size_t)chunk * CHUNK * Id + i;

    float P = 1.f, Q = 0.f;
#pragma unroll 8
    for (int t = 0; t < CHUNK; t++) {
        const float d  = g_decay[base + (size_t)t * Id];
        const float xv = __half2float(xh[base + (size_t)t * Id]);
        P *= d;
        Q = Q * d + (1.f - d) * xv;
    }
    g_P[chunk * NCH + ch] = P;
    g_Q[chunk * NCH + ch] = Q;
}

__global__ void recur_pass2(const __half* __restrict__ xh) {
    const int idx   = blockIdx.x * blockDim.x + threadIdx.x;
    const int ch    = idx & (NCH - 1);
    const int chunk = idx >> 13;
    const int b     = ch >> 10;
    const int i     = ch & (Id - 1);
    size_t base = (size_t)b * Sd * Id + (size_t)chunk * CHUNK * Id + i;

    float buf = 0.f;
    for (int j = 0; j < chunk; j++)
        buf = g_P[j * NCH + ch] * buf + g_Q[j * NCH + ch];

#pragma unroll 8
    for (int t = 0; t < CHUNK; t++) {
        const float d  = g_decay[base + (size_t)t * Id];
        const float xv = __half2float(xh[base + (size_t)t * Id]);
        buf = buf * d + (1.f - d) * xv;
        g_comb[base + (size_t)t * Id] = __float2half_rn(xv * d + buf);
    }
}

// ---------------------------------------------------------------------------
// Launch  (6 launches total; with ncu -s 5 -c 1 the profiled launch should
// be the final K=4096 GEMM)
// ---------------------------------------------------------------------------
extern "C" void kernel_launch(void* const* d_in, const int* in_sizes, int n_in,
                              void* d_out, int out_size) {
    const float* x  = (const float*)d_in[0];
    const float* W1 = (const float*)d_in[1];
    const float* b1 = (const float*)d_in[2];
    const float* W2 = (const float*)d_in[3];
    const float* b2 = (const float*)d_in[4];
    const float* Wg = (const float*)d_in[5];
    const float* bg = (const float*)d_in[6];

    __half *xh, *Wgh, *W1h, *W2h, *comb, *hidden;
    float *decay;
    cudaGetSymbolAddress((void**)&xh, g_xh);
    cudaGetSymbolAddress((void**)&Wgh, g_Wgh);
    cudaGetSymbolAddress((void**)&W1h, g_W1h);
    cudaGetSymbolAddress((void**)&W2h, g_W2h);
    cudaGetSymbolAddress((void**)&decay, g_decay);
    cudaGetSymbolAddress((void**)&comb, g_comb);
    cudaGetSymbolAddress((void**)&hidden, g_hidden);

    cudaFuncSetAttribute(gemm_h<0>, cudaFuncAttributeMaxDynamicSharedMemorySize, DYN_SMEM);
    cudaFuncSetAttribute(gemm_h<1>, cudaFuncAttributeMaxDynamicSharedMemorySize, DYN_SMEM);
    cudaFuncSetAttribute(gemm_h<2>, cudaFuncAttributeMaxDynamicSharedMemorySize, DYN_SMEM);

    // 0) fp16 copies of MMA operand inputs (single launch)
    f2hall<<<F2H_TOTAL / 256, 256>>>(x, W1, W2, Wg, xh, W1h, W2h, Wgh);

    // 1) decay = sigmoid(x @ Wg^T + bg)
    gemm_h<2><<<dim3(Id / 128, M_TOT / 128), 128, DYN_SMEM>>>(
        xh, Wgh, bg, decay, M_TOT, Id, Id);
    // 2) recurrence -> combined (fp16), reading fp16 x
    recur_pass1<<<(NCHUNK * NCH) / 256, 256>>>(xh);
    recur_pass2<<<(NCHUNK * NCH) / 256, 256>>>(xh);
    // 3) hidden = relu(combined @ W1^T + b1) -> fp16
    gemm_h<1><<<dim3(Hd / 128, M_TOT / 128), 128, DYN_SMEM>>>(
        comb, W1h, b1, hidden, M_TOT, Hd, Id);
    // 4) out = hidden @ W2^T + b2 -> fp32
    gemm_h<0><<<dim3(Od / 128, M_TOT / 128), 128, DYN_SMEM>>>(
        hidden, W2h, b2, d_out, M_TOT, Od, Hd);
}

// round 12
// speedup vs baseline: 1.6216x; 1.0660x over previous
#include <cuda_runtime.h>
#include <cuda_fp16.h>
#include <cstdint>

// ---------------------------------------------------------------------------
// Problem dims (fixed)
// ---------------------------------------------------------------------------
#define Bd 8
#define Sd 2048
#define Id 1024
#define Hd 4096
#define Od 1024
#define M_TOT (Bd * Sd)          // 16384

#define NCHUNK 64
#define CHUNK  32                // NCHUNK*CHUNK == Sd
#define NCH    (Bd * Id)         // 8192 channels
#define NPAIR  (NCH / 2)         // 4096 channel-pairs

// ---------------------------------------------------------------------------
// Scratch (__device__ globals, allocation-free)
// ---------------------------------------------------------------------------
__device__ __half g_xh[(size_t)M_TOT * Id];        // 32 MB
__device__ __half g_Wgh[(size_t)Id * Id];          //  2 MB
__device__ __half g_W1h[(size_t)Hd * Id];          //  8 MB
__device__ __half g_W2h[(size_t)Od * Hd];          //  8 MB
__device__ float  g_decay[(size_t)M_TOT * Id];     // 64 MB
__device__ __half g_comb[(size_t)M_TOT * Id];      // 32 MB
__device__ __half g_hidden[(size_t)M_TOT * Hd];    // 128 MB
__device__ float2 g_P2[NCHUNK * NPAIR];            // 2 MB
__device__ float2 g_Q2[NCHUNK * NPAIR];            // 2 MB

// ---------------------------------------------------------------------------
// PTX helpers
// ---------------------------------------------------------------------------
__device__ __forceinline__ uint32_t smem_u32(const void* p) {
    uint32_t a;
    asm("{ .reg .u64 t; cvta.to.shared.u64 t, %1; cvt.u32.u64 %0, t; }"
        : "=r"(a) : "l"(p));
    return a;
}

#define CP_ASYNC16(dst, src) \
    asm volatile("cp.async.cg.shared.global [%0], [%1], 16;" :: "r"(dst), "l"(src))
#define CP_COMMIT() asm volatile("cp.async.commit_group;" ::: "memory")
#define CP_WAIT(n)  asm volatile("cp.async.wait_group %0;" :: "n"(n) : "memory")

#define LDSM_X4(r0, r1, r2, r3, addr)                                        \
    asm volatile("ldmatrix.sync.aligned.m8n8.x4.shared.b16 {%0,%1,%2,%3}, [%4];" \
        : "=r"(r0), "=r"(r1), "=r"(r2), "=r"(r3) : "r"(addr))

__device__ __forceinline__ void mma16(float c[4], const uint32_t a[4], const uint32_t b[2]) {
    asm volatile(
        "mma.sync.aligned.m16n8k16.row.col.f32.f16.f16.f32 "
        "{%0,%1,%2,%3}, {%4,%5,%6,%7}, {%8,%9}, {%0,%1,%2,%3};"
        : "+f"(c[0]), "+f"(c[1]), "+f"(c[2]), "+f"(c[3])
        : "r"(a[0]), "r"(a[1]), "r"(a[2]), "r"(a[3]), "r"(b[0]), "r"(b[1]));
}

// ---------------------------------------------------------------------------
// fp16 GEMM (unchanged from the 833us kernel): CTA 128x128, 4 warps 64x64,
// K-slab 64, 2-stage cp.async, fragment double-buffering, early buffer
// handoff. EPI: 0 = none (f32 out), 1 = relu (f16 out), 2 = sigmoid (f32 out)
// ---------------------------------------------------------------------------
#define KSLAB 64
#define ATILE 16384                   // 128 rows * 128 B
#define STAGE (2 * ATILE)             // A + B = 32 KB
#define DYN_SMEM (2 * STAGE)          // 64 KB

__device__ __forceinline__ void fill_slab(uint32_t sbuf, const __half* ga,
                                          const __half* gb, int K, int k0, int tid) {
    const int r0 = tid >> 3;          // 0..15
    const int c  = tid & 7;           // 16B chunk within 128B row
#pragma unroll
    for (int q = 0; q < 8; q++) {
        const int row = r0 + q * 16;
        const uint32_t sw = (uint32_t)((c ^ (row & 7)) << 4);
        CP_ASYNC16(sbuf + row * 128 + sw, ga + (size_t)row * K + k0 + c * 8);
    }
#pragma unroll
    for (int q = 0; q < 8; q++) {
        const int row = r0 + q * 16;
        const uint32_t sw = (uint32_t)((c ^ (row & 7)) << 4);
        CP_ASYNC16(sbuf + ATILE + row * 128 + sw, gb + (size_t)row * K + k0 + c * 8);
    }
}

struct FragCoords {
    int rA, cA, xA, rB, cB, xB;
};

__device__ __forceinline__ void load_frags(uint32_t buf, int kk,
                                           uint32_t af[4][4], uint32_t bf[8][2],
                                           const FragCoords& fc) {
#pragma unroll
    for (int mt = 0; mt < 4; mt++) {
        const uint32_t addr = buf + (fc.rA + mt * 16) * 128 +
                              (uint32_t)(((kk * 2 + fc.cA) ^ fc.xA) << 4);
        LDSM_X4(af[mt][0], af[mt][1], af[mt][2], af[mt][3], addr);
    }
#pragma unroll
    for (int p = 0; p < 4; p++) {
        const uint32_t addr = buf + ATILE + (fc.rB + p * 16) * 128 +
                              (uint32_t)(((kk * 2 + fc.cB) ^ fc.xB) << 4);
        LDSM_X4(bf[2 * p][0], bf[2 * p][1], bf[2 * p + 1][0], bf[2 * p + 1][1], addr);
    }
}

template <int EPI>
__global__ void __launch_bounds__(128, 2)
gemm_h(const __half* __restrict__ A, const __half* __restrict__ Bm,
       const float* __restrict__ bias, void* __restrict__ Cout,
       int M, int N, int K) {
    extern __shared__ char smem[];
    const uint32_t sb = smem_u32(smem);

    const int tid  = threadIdx.x;
    const int lane = tid & 31;
    const int warp = tid >> 5;
    const int g    = lane >> 2;
    const int tig  = lane & 3;
    const int wm   = (warp >> 1) * 64;
    const int wn   = (warp & 1) * 64;

    FragCoords fc;
    fc.rA = wm + (lane & 15);
    fc.cA = lane >> 4;
    fc.xA = fc.rA & 7;
    fc.rB = wn + (lane & 7) + ((lane >> 4) << 3);
    fc.cB = (lane >> 3) & 1;
    fc.xB = fc.rB & 7;

    const size_t blockM = (size_t)blockIdx.y * 128;
    const size_t blockN = (size_t)blockIdx.x * 128;
    const __half* ga = A  + blockM * (size_t)K;
    const __half* gb = Bm + blockN * (size_t)K;

    float c[4][8][4] = {};

    const int nk = K / KSLAB;
    fill_slab(sb,         ga, gb, K, 0,     tid); CP_COMMIT();
    fill_slab(sb + STAGE, ga, gb, K, KSLAB, tid); CP_COMMIT();

    for (int kt = 0; kt < nk; kt++) {
        CP_WAIT(1);
        __syncthreads();

        const uint32_t buf = sb + (kt & 1) * STAGE;
        uint32_t af[2][4][4], bf[2][8][2];
        load_frags(buf, 0, af[0], bf[0], fc);

#pragma unroll
        for (int kk = 0; kk < 4; kk++) {
            const int cur = kk & 1;
            if (kk < 3) {
                load_frags(buf, kk + 1, af[cur ^ 1], bf[cur ^ 1], fc);
            } else {
                __syncthreads();
                if (kt + 2 < nk)
                    fill_slab(buf, ga, gb, K, (kt + 2) * KSLAB, tid);
                CP_COMMIT();
            }
#pragma unroll
            for (int mt = 0; mt < 4; mt++)
#pragma unroll
                for (int nt = 0; nt < 8; nt++)
                    mma16(c[mt][nt], af[cur][mt], bf[cur][nt]);
        }
    }

    // ---- epilogue ----
#pragma unroll
    for (int mt = 0; mt < 4; mt++) {
#pragma unroll
        for (int nt = 0; nt < 8; nt++) {
            const size_t row = blockM + wm + mt * 16 + g;
            const size_t col = blockN + wn + nt * 8 + 2 * tig;
            const float bv0 = __ldg(bias + col);
            const float bv1 = __ldg(bias + col + 1);
            float v00 = c[mt][nt][0] + bv0, v01 = c[mt][nt][1] + bv1;
            float v10 = c[mt][nt][2] + bv0, v11 = c[mt][nt][3] + bv1;
            if (EPI == 1) {
                v00 = v00 > 0.f ? v00 : 0.f;  v01 = v01 > 0.f ? v01 : 0.f;
                v10 = v10 > 0.f ? v10 : 0.f;  v11 = v11 > 0.f ? v11 : 0.f;
                __half* Ch = (__half*)Cout;
                *reinterpret_cast<__half2*>(&Ch[row * N + col]) =
                    __floats2half2_rn(v00, v01);
                *reinterpret_cast<__half2*>(&Ch[(row + 8) * N + col]) =
                    __floats2half2_rn(v10, v11);
            } else {
                if (EPI == 2) {
                    v00 = 1.f / (1.f + __expf(-v00)); v01 = 1.f / (1.f + __expf(-v01));
                    v10 = 1.f / (1.f + __expf(-v10)); v11 = 1.f / (1.f + __expf(-v11));
                }
                float* Cf = (float*)Cout;
                *reinterpret_cast<float2*>(&Cf[row * N + col]) = make_float2(v00, v01);
                *reinterpret_cast<float2*>(&Cf[(row + 8) * N + col]) = make_float2(v10, v11);
            }
        }
    }
}

// ---------------------------------------------------------------------------
// Merged fp32 -> fp16 conversion (single launch; clock canary ~11-12us fast)
// ---------------------------------------------------------------------------
#define F2H_N4_X  4194304
#define F2H_N4_W1 1048576
#define F2H_N4_W2 1048576
#define F2H_N4_WG 262144
#define F2H_TOTAL (F2H_N4_X + F2H_N4_W1 + F2H_N4_W2 + F2H_N4_WG)

__global__ void f2hall(const float* __restrict__ x,  const float* __restrict__ W1,
                       const float* __restrict__ W2, const float* __restrict__ Wg,
                       __half* __restrict__ xh,  __half* __restrict__ W1h,
                       __half* __restrict__ W2h, __half* __restrict__ Wgh) {
    int i = blockIdx.x * blockDim.x + threadIdx.x;
    const float* src;
    __half* dst;
    if (i < F2H_N4_X)                      { src = x;  dst = xh; }
    else if (i < F2H_N4_X + F2H_N4_W1)     { src = W1; dst = W1h; i -= F2H_N4_X; }
    else if (i < F2H_N4_X + F2H_N4_W1 + F2H_N4_W2)
                                           { src = W2; dst = W2h; i -= F2H_N4_X + F2H_N4_W1; }
    else                                   { src = Wg; dst = Wgh; i -= F2H_N4_X + F2H_N4_W1 + F2H_N4_W2; }
    float4 v = reinterpret_cast<const float4*>(src)[i];
    __half2 h0 = __floats2half2_rn(v.x, v.y);
    __half2 h1 = __floats2half2_rn(v.z, v.w);
    uint2 u;
    u.x = *reinterpret_cast<uint32_t*>(&h0);
    u.y = *reinterpret_cast<uint32_t*>(&h1);
    reinterpret_cast<uint2*>(dst)[i] = u;
}

// ---------------------------------------------------------------------------
// Recurrence, MLP-optimized: 64 chunks of 32 steps, 2 channels per thread
// (float2 decay loads, half2 x loads / comb stores). 262144 threads.
// ---------------------------------------------------------------------------
__global__ void recur_pass1(const __half* __restrict__ xh) {
    const int idx   = blockIdx.x * blockDim.x + threadIdx.x;   // 0..NCHUNK*NPAIR-1
    const int pr    = idx & (NPAIR - 1);
    const int chunk = idx >> 12;                // / NPAIR
    const int b     = pr >> 9;                  // / (Id/2)
    const int i     = (pr & 511) << 1;          // channel
    const size_t base = (size_t)b * Sd * Id + (size_t)chunk * CHUNK * Id + i;

    float Px = 1.f, Py = 1.f, Qx = 0.f, Qy = 0.f;
#pragma unroll 8
    for (int t = 0; t < CHUNK; t++) {
        const float2 d = *reinterpret_cast<const float2*>(g_decay + base + (size_t)t * Id);
        const float2 xv = __half22float2(
            *reinterpret_cast<const __half2*>(xh + base + (size_t)t * Id));
        Px *= d.x;                        Py *= d.y;
        Qx = Qx * d.x + (1.f - d.x) * xv.x;
        Qy = Qy * d.y + (1.f - d.y) * xv.y;
    }
    g_P2[chunk * NPAIR + pr] = make_float2(Px, Py);
    g_Q2[chunk * NPAIR + pr] = make_float2(Qx, Qy);
}

__global__ void recur_pass2(const __half* __restrict__ xh) {
    const int idx   = blockIdx.x * blockDim.x + threadIdx.x;
    const int pr    = idx & (NPAIR - 1);
    const int chunk = idx >> 12;
    const int b     = pr >> 9;
    const int i     = (pr & 511) << 1;
    const size_t base = (size_t)b * Sd * Id + (size_t)chunk * CHUNK * Id + i;

    float bx = 0.f, by = 0.f;
    for (int j = 0; j < chunk; j++) {
        const float2 P = g_P2[j * NPAIR + pr];
        const float2 Q = g_Q2[j * NPAIR + pr];
        bx = P.x * bx + Q.x;
        by = P.y * by + Q.y;
    }

#pragma unroll 8
    for (int t = 0; t < CHUNK; t++) {
        const float2 d = *reinterpret_cast<const float2*>(g_decay + base + (size_t)t * Id);
        const float2 xv = __half22float2(
            *reinterpret_cast<const __half2*>(xh + base + (size_t)t * Id));
        bx = bx * d.x + (1.f - d.x) * xv.x;
        by = by * d.y + (1.f - d.y) * xv.y;
        *reinterpret_cast<__half2*>(g_comb + base + (size_t)t * Id) =
            __floats2half2_rn(xv.x * d.x + bx, xv.y * d.y + by);
    }
}

// ---------------------------------------------------------------------------
// Launch
// ---------------------------------------------------------------------------
extern "C" void kernel_launch(void* const* d_in, const int* in_sizes, int n_in,
                              void* d_out, int out_size) {
    const float* x  = (const float*)d_in[0];
    const float* W1 = (const float*)d_in[1];
    const float* b1 = (const float*)d_in[2];
    const float* W2 = (const float*)d_in[3];
    const float* b2 = (const float*)d_in[4];
    const float* Wg = (const float*)d_in[5];
    const float* bg = (const float*)d_in[6];

    __half *xh, *Wgh, *W1h, *W2h, *comb, *hidden;
    float *decay;
    cudaGetSymbolAddress((void**)&xh, g_xh);
    cudaGetSymbolAddress((void**)&Wgh, g_Wgh);
    cudaGetSymbolAddress((void**)&W1h, g_W1h);
    cudaGetSymbolAddress((void**)&W2h, g_W2h);
    cudaGetSymbolAddress((void**)&decay, g_decay);
    cudaGetSymbolAddress((void**)&comb, g_comb);
    cudaGetSymbolAddress((void**)&hidden, g_hidden);

    cudaFuncSetAttribute(gemm_h<0>, cudaFuncAttributeMaxDynamicSharedMemorySize, DYN_SMEM);
    cudaFuncSetAttribute(gemm_h<1>, cudaFuncAttributeMaxDynamicSharedMemorySize, DYN_SMEM);
    cudaFuncSetAttribute(gemm_h<2>, cudaFuncAttributeMaxDynamicSharedMemorySize, DYN_SMEM);

    // 0) fp16 copies of MMA operand inputs (single launch)
    f2hall<<<F2H_TOTAL / 256, 256>>>(x, W1, W2, Wg, xh, W1h, W2h, Wgh);

    // 1) decay = sigmoid(x @ Wg^T + bg)
    gemm_h<2><<<dim3(Id / 128, M_TOT / 128), 128, DYN_SMEM>>>(
        xh, Wgh, bg, decay, M_TOT, Id, Id);
    // 2) recurrence -> combined (fp16)
    recur_pass1<<<(NCHUNK * NPAIR) / 256, 256>>>(xh);
    recur_pass2<<<(NCHUNK * NPAIR) / 256, 256>>>(xh);
    // 3) hidden = relu(combined @ W1^T + b1) -> fp16
    gemm_h<1><<<dim3(Hd / 128, M_TOT / 128), 128, DYN_SMEM>>>(
        comb, W1h, b1, hidden, M_TOT, Hd, Id);
    // 4) out = hidden @ W2^T + b2 -> fp32
    gemm_h<0><<<dim3(Od / 128, M_TOT / 128), 128, DYN_SMEM>>>(
        hidden, W2h, b2, d_out, M_TOT, Od, Hd);
}

// round 13
// speedup vs baseline: 1.6318x; 1.0063x over previous
#include <cuda_runtime.h>
#include <cuda_fp16.h>
#include <cstdint>

// ---------------------------------------------------------------------------
// Problem dims (fixed)
// ---------------------------------------------------------------------------
#define Bd 8
#define Sd 2048
#define Id 1024
#define Hd 4096
#define Od 1024
#define M_TOT (Bd * Sd)          // 16384

#define NCHUNK 64
#define CHUNK  32                // NCHUNK*CHUNK == Sd
#define NCH    (Bd * Id)         // 8192 channels
#define NPAIR  (NCH / 2)         // 4096 channel-pairs
#define TBATCH 8                 // timesteps batched per load group

// ---------------------------------------------------------------------------
// Scratch (__device__ globals, allocation-free)
// ---------------------------------------------------------------------------
__device__ __half g_xh[(size_t)M_TOT * Id];        // 32 MB
__device__ __half g_Wgh[(size_t)Id * Id];          //  2 MB
__device__ __half g_W1h[(size_t)Hd * Id];          //  8 MB
__device__ __half g_W2h[(size_t)Od * Hd];          //  8 MB
__device__ float  g_decay[(size_t)M_TOT * Id];     // 64 MB
__device__ __half g_comb[(size_t)M_TOT * Id];      // 32 MB
__device__ __half g_hidden[(size_t)M_TOT * Hd];    // 128 MB
__device__ float2 g_P2[NCHUNK * NPAIR];            // 2 MB
__device__ float2 g_Q2[NCHUNK * NPAIR];            // 2 MB

// ---------------------------------------------------------------------------
// PTX helpers
// ---------------------------------------------------------------------------
__device__ __forceinline__ uint32_t smem_u32(const void* p) {
    uint32_t a;
    asm("{ .reg .u64 t; cvta.to.shared.u64 t, %1; cvt.u32.u64 %0, t; }"
        : "=r"(a) : "l"(p));
    return a;
}

#define CP_ASYNC16(dst, src) \
    asm volatile("cp.async.cg.shared.global [%0], [%1], 16;" :: "r"(dst), "l"(src))
#define CP_COMMIT() asm volatile("cp.async.commit_group;" ::: "memory")
#define CP_WAIT(n)  asm volatile("cp.async.wait_group %0;" :: "n"(n) : "memory")

#define LDSM_X4(r0, r1, r2, r3, addr)                                        \
    asm volatile("ldmatrix.sync.aligned.m8n8.x4.shared.b16 {%0,%1,%2,%3}, [%4];" \
        : "=r"(r0), "=r"(r1), "=r"(r2), "=r"(r3) : "r"(addr))

__device__ __forceinline__ void mma16(float c[4], const uint32_t a[4], const uint32_t b[2]) {
    asm volatile(
        "mma.sync.aligned.m16n8k16.row.col.f32.f16.f16.f32 "
        "{%0,%1,%2,%3}, {%4,%5,%6,%7}, {%8,%9}, {%0,%1,%2,%3};"
        : "+f"(c[0]), "+f"(c[1]), "+f"(c[2]), "+f"(c[3])
        : "r"(a[0]), "r"(a[1]), "r"(a[2]), "r"(a[3]), "r"(b[0]), "r"(b[1]));
}

// ---------------------------------------------------------------------------
// fp16 GEMM (unchanged from the 770us kernel): CTA 128x128, 4 warps 64x64,
// K-slab 64, 2-stage cp.async, fragment double-buffering, early buffer
// handoff. EPI: 0 = none (f32 out), 1 = relu (f16 out), 2 = sigmoid (f32 out)
// ---------------------------------------------------------------------------
#define KSLAB 64
#define ATILE 16384                   // 128 rows * 128 B
#define STAGE (2 * ATILE)             // A + B = 32 KB
#define DYN_SMEM (2 * STAGE)          // 64 KB

__device__ __forceinline__ void fill_slab(uint32_t sbuf, const __half* ga,
                                          const __half* gb, int K, int k0, int tid) {
    const int r0 = tid >> 3;          // 0..15
    const int c  = tid & 7;           // 16B chunk within 128B row
#pragma unroll
    for (int q = 0; q < 8; q++) {
        const int row = r0 + q * 16;
        const uint32_t sw = (uint32_t)((c ^ (row & 7)) << 4);
        CP_ASYNC16(sbuf + row * 128 + sw, ga + (size_t)row * K + k0 + c * 8);
    }
#pragma unroll
    for (int q = 0; q < 8; q++) {
        const int row = r0 + q * 16;
        const uint32_t sw = (uint32_t)((c ^ (row & 7)) << 4);
        CP_ASYNC16(sbuf + ATILE + row * 128 + sw, gb + (size_t)row * K + k0 + c * 8);
    }
}

struct FragCoords {
    int rA, cA, xA, rB, cB, xB;
};

__device__ __forceinline__ void load_frags(uint32_t buf, int kk,
                                           uint32_t af[4][4], uint32_t bf[8][2],
                                           const FragCoords& fc) {
#pragma unroll
    for (int mt = 0; mt < 4; mt++) {
        const uint32_t addr = buf + (fc.rA + mt * 16) * 128 +
                              (uint32_t)(((kk * 2 + fc.cA) ^ fc.xA) << 4);
        LDSM_X4(af[mt][0], af[mt][1], af[mt][2], af[mt][3], addr);
    }
#pragma unroll
    for (int p = 0; p < 4; p++) {
        const uint32_t addr = buf + ATILE + (fc.rB + p * 16) * 128 +
                              (uint32_t)(((kk * 2 + fc.cB) ^ fc.xB) << 4);
        LDSM_X4(bf[2 * p][0], bf[2 * p][1], bf[2 * p + 1][0], bf[2 * p + 1][1], addr);
    }
}

template <int EPI>
__global__ void __launch_bounds__(128, 2)
gemm_h(const __half* __restrict__ A, const __half* __restrict__ Bm,
       const float* __restrict__ bias, void* __restrict__ Cout,
       int M, int N, int K) {
    extern __shared__ char smem[];
    const uint32_t sb = smem_u32(smem);

    const int tid  = threadIdx.x;
    const int lane = tid & 31;
    const int warp = tid >> 5;
    const int g    = lane >> 2;
    const int tig  = lane & 3;
    const int wm   = (warp >> 1) * 64;
    const int wn   = (warp & 1) * 64;

    FragCoords fc;
    fc.rA = wm + (lane & 15);
    fc.cA = lane >> 4;
    fc.xA = fc.rA & 7;
    fc.rB = wn + (lane & 7) + ((lane >> 4) << 3);
    fc.cB = (lane >> 3) & 1;
    fc.xB = fc.rB & 7;

    const size_t blockM = (size_t)blockIdx.y * 128;
    const size_t blockN = (size_t)blockIdx.x * 128;
    const __half* ga = A  + blockM * (size_t)K;
    const __half* gb = Bm + blockN * (size_t)K;

    float c[4][8][4] = {};

    const int nk = K / KSLAB;
    fill_slab(sb,         ga, gb, K, 0,     tid); CP_COMMIT();
    fill_slab(sb + STAGE, ga, gb, K, KSLAB, tid); CP_COMMIT();

    for (int kt = 0; kt < nk; kt++) {
        CP_WAIT(1);
        __syncthreads();

        const uint32_t buf = sb + (kt & 1) * STAGE;
        uint32_t af[2][4][4], bf[2][8][2];
        load_frags(buf, 0, af[0], bf[0], fc);

#pragma unroll
        for (int kk = 0; kk < 4; kk++) {
            const int cur = kk & 1;
            if (kk < 3) {
                load_frags(buf, kk + 1, af[cur ^ 1], bf[cur ^ 1], fc);
            } else {
                __syncthreads();
                if (kt + 2 < nk)
                    fill_slab(buf, ga, gb, K, (kt + 2) * KSLAB, tid);
                CP_COMMIT();
            }
#pragma unroll
            for (int mt = 0; mt < 4; mt++)
#pragma unroll
                for (int nt = 0; nt < 8; nt++)
                    mma16(c[mt][nt], af[cur][mt], bf[cur][nt]);
        }
    }

    // ---- epilogue ----
#pragma unroll
    for (int mt = 0; mt < 4; mt++) {
#pragma unroll
        for (int nt = 0; nt < 8; nt++) {
            const size_t row = blockM + wm + mt * 16 + g;
            const size_t col = blockN + wn + nt * 8 + 2 * tig;
            const float bv0 = __ldg(bias + col);
            const float bv1 = __ldg(bias + col + 1);
            float v00 = c[mt][nt][0] + bv0, v01 = c[mt][nt][1] + bv1;
            float v10 = c[mt][nt][2] + bv0, v11 = c[mt][nt][3] + bv1;
            if (EPI == 1) {
                v00 = v00 > 0.f ? v00 : 0.f;  v01 = v01 > 0.f ? v01 : 0.f;
                v10 = v10 > 0.f ? v10 : 0.f;  v11 = v11 > 0.f ? v11 : 0.f;
                __half* Ch = (__half*)Cout;
                *reinterpret_cast<__half2*>(&Ch[row * N + col]) =
                    __floats2half2_rn(v00, v01);
                *reinterpret_cast<__half2*>(&Ch[(row + 8) * N + col]) =
                    __floats2half2_rn(v10, v11);
            } else {
                if (EPI == 2) {
                    v00 = 1.f / (1.f + __expf(-v00)); v01 = 1.f / (1.f + __expf(-v01));
                    v10 = 1.f / (1.f + __expf(-v10)); v11 = 1.f / (1.f + __expf(-v11));
                }
                float* Cf = (float*)Cout;
                *reinterpret_cast<float2*>(&Cf[row * N + col]) = make_float2(v00, v01);
                *reinterpret_cast<float2*>(&Cf[(row + 8) * N + col]) = make_float2(v10, v11);
            }
        }
    }
}

// ---------------------------------------------------------------------------
// Merged fp32 -> fp16 conversion (single launch; clock canary ~11-13us fast)
// ---------------------------------------------------------------------------
#define F2H_N4_X  4194304
#define F2H_N4_W1 1048576
#define F2H_N4_W2 1048576
#define F2H_N4_WG 262144
#define F2H_TOTAL (F2H_N4_X + F2H_N4_W1 + F2H_N4_W2 + F2H_N4_WG)

__global__ void f2hall(const float* __restrict__ x,  const float* __restrict__ W1,
                       const float* __restrict__ W2, const float* __restrict__ Wg,
                       __half* __restrict__ xh,  __half* __restrict__ W1h,
                       __half* __restrict__ W2h, __half* __restrict__ Wgh) {
    int i = blockIdx.x * blockDim.x + threadIdx.x;
    const float* src;
    __half* dst;
    if (i < F2H_N4_X)                      { src = x;  dst = xh; }
    else if (i < F2H_N4_X + F2H_N4_W1)     { src = W1; dst = W1h; i -= F2H_N4_X; }
    else if (i < F2H_N4_X + F2H_N4_W1 + F2H_N4_W2)
                                           { src = W2; dst = W2h; i -= F2H_N4_X + F2H_N4_W1; }
    else                                   { src = Wg; dst = Wgh; i -= F2H_N4_X + F2H_N4_W1 + F2H_N4_W2; }
    float4 v = reinterpret_cast<const float4*>(src)[i];
    __half2 h0 = __floats2half2_rn(v.x, v.y);
    __half2 h1 = __floats2half2_rn(v.z, v.w);
    uint2 u;
    u.x = *reinterpret_cast<uint32_t*>(&h0);
    u.y = *reinterpret_cast<uint32_t*>(&h1);
    reinterpret_cast<uint2*>(dst)[i] = u;
}

// ---------------------------------------------------------------------------
// Recurrence: 64 chunks of 32 steps, 2 channels/thread, and now explicit
// 8-timestep load batching (16 loads in flight per thread) to force MLP.
// Arithmetic order identical to the unbatched version.
// ---------------------------------------------------------------------------
__global__ void recur_pass1(const __half* __restrict__ xh) {
    const int idx   = blockIdx.x * blockDim.x + threadIdx.x;   // 0..NCHUNK*NPAIR-1
    const int pr    = idx & (NPAIR - 1);
    const int chunk = idx >> 12;                // / NPAIR
    const int b     = pr >> 9;                  // / (Id/2)
    const int i     = (pr & 511) << 1;          // channel
    const size_t base = (size_t)b * Sd * Id + (size_t)chunk * CHUNK * Id + i;

    float Px = 1.f, Py = 1.f, Qx = 0.f, Qy = 0.f;
#pragma unroll
    for (int t0 = 0; t0 < CHUNK; t0 += TBATCH) {
        float2 d[TBATCH];
        float2 xv[TBATCH];
#pragma unroll
        for (int j = 0; j < TBATCH; j++) {
            d[j]  = *reinterpret_cast<const float2*>(
                g_decay + base + (size_t)(t0 + j) * Id);
            xv[j] = __half22float2(*reinterpret_cast<const __half2*>(
                xh + base + (size_t)(t0 + j) * Id));
        }
#pragma unroll
        for (int j = 0; j < TBATCH; j++) {
            Px *= d[j].x;                        Py *= d[j].y;
            Qx = Qx * d[j].x + (1.f - d[j].x) * xv[j].x;
            Qy = Qy * d[j].y + (1.f - d[j].y) * xv[j].y;
        }
    }
    g_P2[chunk * NPAIR + pr] = make_float2(Px, Py);
    g_Q2[chunk * NPAIR + pr] = make_float2(Qx, Qy);
}

__global__ void recur_pass2(const __half* __restrict__ xh) {
    const int idx   = blockIdx.x * blockDim.x + threadIdx.x;
    const int pr    = idx & (NPAIR - 1);
    const int chunk = idx >> 12;
    const int b     = pr >> 9;
    const int i     = (pr & 511) << 1;
    const size_t base = (size_t)b * Sd * Id + (size_t)chunk * CHUNK * Id + i;

    float bx = 0.f, by = 0.f;
    for (int j = 0; j < chunk; j++) {
        const float2 P = g_P2[j * NPAIR + pr];
        const float2 Q = g_Q2[j * NPAIR + pr];
        bx = P.x * bx + Q.x;
        by = P.y * by + Q.y;
    }

#pragma unroll
    for (int t0 = 0; t0 < CHUNK; t0 += TBATCH) {
        float2 d[TBATCH];
        float2 xv[TBATCH];
#pragma unroll
        for (int j = 0; j < TBATCH; j++) {
            d[j]  = *reinterpret_cast<const float2*>(
                g_decay + base + (size_t)(t0 + j) * Id);
            xv[j] = __half22float2(*reinterpret_cast<const __half2*>(
                xh + base + (size_t)(t0 + j) * Id));
        }
#pragma unroll
        for (int j = 0; j < TBATCH; j++) {
            bx = bx * d[j].x + (1.f - d[j].x) * xv[j].x;
            by = by * d[j].y + (1.f - d[j].y) * xv[j].y;
            *reinterpret_cast<__half2*>(g_comb + base + (size_t)(t0 + j) * Id) =
                __floats2half2_rn(xv[j].x * d[j].x + bx, xv[j].y * d[j].y + by);
        }
    }
}

// ---------------------------------------------------------------------------
// Launch
// ---------------------------------------------------------------------------
extern "C" void kernel_launch(void* const* d_in, const int* in_sizes, int n_in,
                              void* d_out, int out_size) {
    const float* x  = (const float*)d_in[0];
    const float* W1 = (const float*)d_in[1];
    const float* b1 = (const float*)d_in[2];
    const float* W2 = (const float*)d_in[3];
    const float* b2 = (const float*)d_in[4];
    const float* Wg = (const float*)d_in[5];
    const float* bg = (const float*)d_in[6];

    __half *xh, *Wgh, *W1h, *W2h, *comb, *hidden;
    float *decay;
    cudaGetSymbolAddress((void**)&xh, g_xh);
    cudaGetSymbolAddress((void**)&Wgh, g_Wgh);
    cudaGetSymbolAddress((void**)&W1h, g_W1h);
    cudaGetSymbolAddress((void**)&W2h, g_W2h);
    cudaGetSymbolAddress((void**)&decay, g_decay);
    cudaGetSymbolAddress((void**)&comb, g_comb);
    cudaGetSymbolAddress((void**)&hidden, g_hidden);

    cudaFuncSetAttribute(gemm_h<0>, cudaFuncAttributeMaxDynamicSharedMemorySize, DYN_SMEM);
    cudaFuncSetAttribute(gemm_h<1>, cudaFuncAttributeMaxDynamicSharedMemorySize, DYN_SMEM);
    cudaFuncSetAttribute(gemm_h<2>, cudaFuncAttributeMaxDynamicSharedMemorySize, DYN_SMEM);

    // 0) fp16 copies of MMA operand inputs (single launch)
    f2hall<<<F2H_TOTAL / 256, 256>>>(x, W1, W2, Wg, xh, W1h, W2h, Wgh);

    // 1) decay = sigmoid(x @ Wg^T + bg)
    gemm_h<2><<<dim3(Id / 128, M_TOT / 128), 128, DYN_SMEM>>>(
        xh, Wgh, bg, decay, M_TOT, Id, Id);
    // 2) recurrence -> combined (fp16)
    recur_pass1<<<(NCHUNK * NPAIR) / 256, 256>>>(xh);
    recur_pass2<<<(NCHUNK * NPAIR) / 256, 256>>>(xh);
    // 3) hidden = relu(combined @ W1^T + b1) -> fp16
    gemm_h<1><<<dim3(Hd / 128, M_TOT / 128), 128, DYN_SMEM>>>(
        comb, W1h, b1, hidden, M_TOT, Hd, Id);
    // 4) out = hidden @ W2^T + b2 -> fp32
    gemm_h<0><<<dim3(Od / 128, M_TOT / 128), 128, DYN_SMEM>>>(
        hidden, W2h, b2, d_out, M_TOT, Od, Hd);
}

// round 15
// speedup vs baseline: 1.6697x; 1.0232x over previous
#include <cuda_runtime.h>
#include <cuda_fp16.h>
#include <cstdint>

// ---------------------------------------------------------------------------
// Problem dims (fixed)
// ---------------------------------------------------------------------------
#define Bd 8
#define Sd 2048
#define Id 1024
#define Hd 4096
#define Od 1024
#define M_TOT (Bd * Sd)          // 16384

#define NCHUNK 64
#define CHUNK  32                // NCHUNK*CHUNK == Sd
#define NCH    (Bd * Id)         // 8192 channels
#define NPAIR  (NCH / 2)         // 4096 channel-pairs
#define TBATCH 8                 // timesteps batched per load group

// ---------------------------------------------------------------------------
// Scratch (__device__ globals, allocation-free)
// ---------------------------------------------------------------------------
__device__ __half g_xh[(size_t)M_TOT * Id];        // 32 MB
__device__ __half g_Wgh[(size_t)Id * Id];          //  2 MB
__device__ __half g_W1h[(size_t)Hd * Id];          //  8 MB
__device__ __half g_W2h[(size_t)Od * Hd];          //  8 MB
__device__ __half g_decayh[(size_t)M_TOT * Id];    // 32 MB (fp16 decay)
__device__ __half g_comb[(size_t)M_TOT * Id];      // 32 MB
__device__ __half g_hidden[(size_t)M_TOT * Hd];    // 128 MB
__device__ float2 g_P2[NCHUNK * NPAIR];            // 2 MB
__device__ float2 g_Q2[NCHUNK * NPAIR];            // 2 MB

// ---------------------------------------------------------------------------
// PTX helpers
// ---------------------------------------------------------------------------
__device__ __forceinline__ uint32_t smem_u32(const void* p) {
    uint32_t a;
    asm("{ .reg .u64 t; cvta.to.shared.u64 t, %1; cvt.u32.u64 %0, t; }"
        : "=r"(a) : "l"(p));
    return a;
}

#define CP_ASYNC16(dst, src) \
    asm volatile("cp.async.cg.shared.global [%0], [%1], 16;" :: "r"(dst), "l"(src))
#define CP_COMMIT() asm volatile("cp.async.commit_group;" ::: "memory")
#define CP_WAIT(n)  asm volatile("cp.async.wait_group %0;" :: "n"(n) : "memory")

#define LDSM_X4(r0, r1, r2, r3, addr)                                        \
    asm volatile("ldmatrix.sync.aligned.m8n8.x4.shared.b16 {%0,%1,%2,%3}, [%4];" \
        : "=r"(r0), "=r"(r1), "=r"(r2), "=r"(r3) : "r"(addr))

__device__ __forceinline__ void mma16(float c[4], const uint32_t a[4], const uint32_t b[2]) {
    asm volatile(
        "mma.sync.aligned.m16n8k16.row.col.f32.f16.f16.f32 "
        "{%0,%1,%2,%3}, {%4,%5,%6,%7}, {%8,%9}, {%0,%1,%2,%3};"
        : "+f"(c[0]), "+f"(c[1]), "+f"(c[2]), "+f"(c[3])
        : "r"(a[0]), "r"(a[1]), "r"(a[2]), "r"(a[3]), "r"(b[0]), "r"(b[1]));
}

// ---------------------------------------------------------------------------
// fp16 GEMM: CTA 128x128, 4 warps 64x64, K-slab 64, 2-stage cp.async,
// fragment double-buffering, early buffer handoff.
// EPI: 0 = none (f32 out), 1 = relu (f16 out), 2 = sigmoid (f16 out)
// ---------------------------------------------------------------------------
#define KSLAB 64
#define ATILE 16384                   // 128 rows * 128 B
#define STAGE (2 * ATILE)             // A + B = 32 KB
#define DYN_SMEM (2 * STAGE)          // 64 KB

__device__ __forceinline__ void fill_slab(uint32_t sbuf, const __half* ga,
                                          const __half* gb, int K, int k0, int tid) {
    const int r0 = tid >> 3;          // 0..15
    const int c  = tid & 7;           // 16B chunk within 128B row
#pragma unroll
    for (int q = 0; q < 8; q++) {
        const int row = r0 + q * 16;
        const uint32_t sw = (uint32_t)((c ^ (row & 7)) << 4);
        CP_ASYNC16(sbuf + row * 128 + sw, ga + (size_t)row * K + k0 + c * 8);
    }
#pragma unroll
    for (int q = 0; q < 8; q++) {
        const int row = r0 + q * 16;
        const uint32_t sw = (uint32_t)((c ^ (row & 7)) << 4);
        CP_ASYNC16(sbuf + ATILE + row * 128 + sw, gb + (size_t)row * K + k0 + c * 8);
    }
}

struct FragCoords {
    int rA, cA, xA, rB, cB, xB;
};

__device__ __forceinline__ void load_frags(uint32_t buf, int kk,
                                           uint32_t af[4][4], uint32_t bf[8][2],
                                           const FragCoords& fc) {
#pragma unroll
    for (int mt = 0; mt < 4; mt++) {
        const uint32_t addr = buf + (fc.rA + mt * 16) * 128 +
                              (uint32_t)(((kk * 2 + fc.cA) ^ fc.xA) << 4);
        LDSM_X4(af[mt][0], af[mt][1], af[mt][2], af[mt][3], addr);
    }
#pragma unroll
    for (int p = 0; p < 4; p++) {
        const uint32_t addr = buf + ATILE + (fc.rB + p * 16) * 128 +
                              (uint32_t)(((kk * 2 + fc.cB) ^ fc.xB) << 4);
        LDSM_X4(bf[2 * p][0], bf[2 * p][1], bf[2 * p + 1][0], bf[2 * p + 1][1], addr);
    }
}

template <int EPI>
__global__ void __launch_bounds__(128, 2)
gemm_h(const __half* __restrict__ A, const __half* __restrict__ Bm,
       const float* __restrict__ bias, void* __restrict__ Cout,
       int M, int N, int K) {
    extern __shared__ char smem[];
    const uint32_t sb = smem_u32(smem);

    const int tid  = threadIdx.x;
    const int lane = tid & 31;
    const int warp = tid >> 5;
    const int g    = lane >> 2;
    const int tig  = lane & 3;
    const int wm   = (warp >> 1) * 64;
    const int wn   = (warp & 1) * 64;

    FragCoords fc;
    fc.rA = wm + (lane & 15);
    fc.cA = lane >> 4;
    fc.xA = fc.rA & 7;
    fc.rB = wn + (lane & 7) + ((lane >> 4) << 3);
    fc.cB = (lane >> 3) & 1;
    fc.xB = fc.rB & 7;

    const size_t blockM = (size_t)blockIdx.y * 128;
    const size_t blockN = (size_t)blockIdx.x * 128;
    const __half* ga = A  + blockM * (size_t)K;
    const __half* gb = Bm + blockN * (size_t)K;

    float c[4][8][4] = {};

    const int nk = K / KSLAB;
    fill_slab(sb,         ga, gb, K, 0,     tid); CP_COMMIT();
    fill_slab(sb + STAGE, ga, gb, K, KSLAB, tid); CP_COMMIT();

    for (int kt = 0; kt < nk; kt++) {
        CP_WAIT(1);
        __syncthreads();

        const uint32_t buf = sb + (kt & 1) * STAGE;
        uint32_t af[2][4][4], bf[2][8][2];
        load_frags(buf, 0, af[0], bf[0], fc);

#pragma unroll
        for (int kk = 0; kk < 4; kk++) {
            const int cur = kk & 1;
            if (kk < 3) {
                load_frags(buf, kk + 1, af[cur ^ 1], bf[cur ^ 1], fc);
            } else {
                __syncthreads();
                if (kt + 2 < nk)
                    fill_slab(buf, ga, gb, K, (kt + 2) * KSLAB, tid);
                CP_COMMIT();
            }
#pragma unroll
            for (int mt = 0; mt < 4; mt++)
#pragma unroll
                for (int nt = 0; nt < 8; nt++)
                    mma16(c[mt][nt], af[cur][mt], bf[cur][nt]);
        }
    }

    // ---- epilogue ----
#pragma unroll
    for (int mt = 0; mt < 4; mt++) {
#pragma unroll
        for (int nt = 0; nt < 8; nt++) {
            const size_t row = blockM + wm + mt * 16 + g;
            const size_t col = blockN + wn + nt * 8 + 2 * tig;
            const float bv0 = __ldg(bias + col);
            const float bv1 = __ldg(bias + col + 1);
            float v00 = c[mt][nt][0] + bv0, v01 = c[mt][nt][1] + bv1;
            float v10 = c[mt][nt][2] + bv0, v11 = c[mt][nt][3] + bv1;
            if (EPI == 1 || EPI == 2) {
                if (EPI == 1) {
                    v00 = v00 > 0.f ? v00 : 0.f;  v01 = v01 > 0.f ? v01 : 0.f;
                    v10 = v10 > 0.f ? v10 : 0.f;  v11 = v11 > 0.f ? v11 : 0.f;
                } else {
                    v00 = 1.f / (1.f + __expf(-v00)); v01 = 1.f / (1.f + __expf(-v01));
                    v10 = 1.f / (1.f + __expf(-v10)); v11 = 1.f / (1.f + __expf(-v11));
                }
                __half* Ch = (__half*)Cout;
                *reinterpret_cast<__half2*>(&Ch[row * N + col]) =
                    __floats2half2_rn(v00, v01);
                *reinterpret_cast<__half2*>(&Ch[(row + 8) * N + col]) =
                    __floats2half2_rn(v10, v11);
            } else {
                float* Cf = (float*)Cout;
                *reinterpret_cast<float2*>(&Cf[row * N + col]) = make_float2(v00, v01);
                *reinterpret_cast<float2*>(&Cf[(row + 8) * N + col]) = make_float2(v10, v11);
            }
        }
    }
}

// ---------------------------------------------------------------------------
// Merged fp32 -> fp16 conversion (single launch; clock canary ~11-13us fast)
// ---------------------------------------------------------------------------
#define F2H_N4_X  4194304
#define F2H_N4_W1 1048576
#define F2H_N4_W2 1048576
#define F2H_N4_WG 262144
#define F2H_TOTAL (F2H_N4_X + F2H_N4_W1 + F2H_N4_W2 + F2H_N4_WG)

__global__ void f2hall(const float* __restrict__ x,  const float* __restrict__ W1,
                       const float* __restrict__ W2, const float* __restrict__ Wg,
                       __half* __restrict__ xh,  __half* __restrict__ W1h,
                       __half* __restrict__ W2h, __half* __restrict__ Wgh) {
    int i = blockIdx.x * blockDim.x + threadIdx.x;
    const float* src;
    __half* dst;
    if (i < F2H_N4_X)                      { src = x;  dst = xh; }
    else if (i < F2H_N4_X + F2H_N4_W1)     { src = W1; dst = W1h; i -= F2H_N4_X; }
    else if (i < F2H_N4_X + F2H_N4_W1 + F2H_N4_W2)
                                           { src = W2; dst = W2h; i -= F2H_N4_X + F2H_N4_W1; }
    else                                   { src = Wg; dst = Wgh; i -= F2H_N4_X + F2H_N4_W1 + F2H_N4_W2; }
    float4 v = reinterpret_cast<const float4*>(src)[i];
    __half2 h0 = __floats2half2_rn(v.x, v.y);
    __half2 h1 = __floats2half2_rn(v.z, v.w);
    uint2 u;
    u.x = *reinterpret_cast<uint32_t*>(&h0);
    u.y = *reinterpret_cast<uint32_t*>(&h1);
    reinterpret_cast<uint2*>(dst)[i] = u;
}

// ---------------------------------------------------------------------------
// Recurrence: 64 chunks of 32 steps, 2 channels/thread, 8-step load batching,
// fp16 decay + fp16 x (8 B/step/thread).
// ---------------------------------------------------------------------------
__global__ void recur_pass1(const __half* __restrict__ xh) {
    const int idx   = blockIdx.x * blockDim.x + threadIdx.x;   // 0..NCHUNK*NPAIR-1
    const int pr    = idx & (NPAIR - 1);
    const int chunk = idx >> 12;                // / NPAIR
    const int b     = pr >> 9;                  // / (Id/2)
    const int i     = (pr & 511) << 1;          // channel
    const size_t base = (size_t)b * Sd * Id + (size_t)chunk * CHUNK * Id + i;

    float Px = 1.f, Py = 1.f, Qx = 0.f, Qy = 0.f;
#pragma unroll
    for (int t0 = 0; t0 < CHUNK; t0 += TBATCH) {
        float2 d[TBATCH];
        float2 xv[TBATCH];
#pragma unroll
        for (int j = 0; j < TBATCH; j++) {
            d[j]  = __half22float2(*reinterpret_cast<const __half2*>(
                g_decayh + base + (size_t)(t0 + j) * Id));
            xv[j] = __half22float2(*reinterpret_cast<const __half2*>(
                xh + base + (size_t)(t0 + j) * Id));
        }
#pragma unroll
        for (int j = 0; j < TBATCH; j++) {
            Px *= d[j].x;                        Py *= d[j].y;
            Qx = Qx * d[j].x + (1.f - d[j].x) * xv[j].x;
            Qy = Qy * d[j].y + (1.f - d[j].y) * xv[j].y;
        }
    }
    g_P2[chunk * NPAIR + pr] = make_float2(Px, Py);
    g_Q2[chunk * NPAIR + pr] = make_float2(Qx, Qy);
}

__global__ void recur_pass2(const __half* __restrict__ xh) {
    const int idx   = blockIdx.x * blockDim.x + threadIdx.x;
    const int pr    = idx & (NPAIR - 1);
    const int chunk = idx >> 12;
    const int b     = pr >> 9;
    const int i     = (pr & 511) << 1;
    const size_t base = (size_t)b * Sd * Id + (size_t)chunk * CHUNK * Id + i;

    float bx = 0.f, by = 0.f;
    for (int j = 0; j < chunk; j++) {
        const float2 P = g_P2[j * NPAIR + pr];
        const float2 Q = g_Q2[j * NPAIR + pr];
        bx = P.x * bx + Q.x;
        by = P.y * by + Q.y;
    }

#pragma unroll
    for (int t0 = 0; t0 < CHUNK; t0 += TBATCH) {
        float2 d[TBATCH];
        float2 xv[TBATCH];
#pragma unroll
        for (int j = 0; j < TBATCH; j++) {
            d[j]  = __half22float2(*reinterpret_cast<const __half2*>(
                g_decayh + base + (size_t)(t0 + j) * Id));
            xv[j] = __half22float2(*reinterpret_cast<const __half2*>(
                xh + base + (size_t)(t0 + j) * Id));
        }
#pragma unroll
        for (int j = 0; j < TBATCH; j++) {
            bx = bx * d[j].x + (1.f - d[j].x) * xv[j].x;
            by = by * d[j].y + (1.f - d[j].y) * xv[j].y;
            *reinterpret_cast<__half2*>(g_comb + base + (size_t)(t0 + j) * Id) =
                __floats2half2_rn(xv[j].x * d[j].x + bx, xv[j].y * d[j].y + by);
        }
    }
}

// ---------------------------------------------------------------------------
// Launch
// ---------------------------------------------------------------------------
extern "C" void kernel_launch(void* const* d_in, const int* in_sizes, int n_in,
                              void* d_out, int out_size) {
    const float* x  = (const float*)d_in[0];
    const float* W1 = (const float*)d_in[1];
    const float* b1 = (const float*)d_in[2];
    const float* W2 = (const float*)d_in[3];
    const float* b2 = (const float*)d_in[4];
    const float* Wg = (const float*)d_in[5];
    const float* bg = (const float*)d_in[6];

    __half *xh, *Wgh, *W1h, *W2h, *decayh, *comb, *hidden;
    cudaGetSymbolAddress((void**)&xh, g_xh);
    cudaGetSymbolAddress((void**)&Wgh, g_Wgh);
    cudaGetSymbolAddress((void**)&W1h, g_W1h);
    cudaGetSymbolAddress((void**)&W2h, g_W2h);
    cudaGetSymbolAddress((void**)&decayh, g_decayh);
    cudaGetSymbolAddress((void**)&comb, g_comb);
    cudaGetSymbolAddress((void**)&hidden, g_hidden);

    cudaFuncSetAttribute(gemm_h<0>, cudaFuncAttributeMaxDynamicSharedMemorySize, DYN_SMEM);
    cudaFuncSetAttribute(gemm_h<1>, cudaFuncAttributeMaxDynamicSharedMemorySize, DYN_SMEM);
    cudaFuncSetAttribute(gemm_h<2>, cudaFuncAttributeMaxDynamicSharedMemorySize, DYN_SMEM);

    // 0) fp16 copies of MMA operand inputs (single launch)
    f2hall<<<F2H_TOTAL / 256, 256>>>(x, W1, W2, Wg, xh, W1h, W2h, Wgh);

    // 1) decay = sigmoid(x @ Wg^T + bg) -> fp16
    gemm_h<2><<<dim3(Id / 128, M_TOT / 128), 128, DYN_SMEM>>>(
        xh, Wgh, bg, decayh, M_TOT, Id, Id);
    // 2) recurrence -> combined (fp16)
    recur_pass1<<<(NCHUNK * NPAIR) / 256, 256>>>(xh);
    recur_pass2<<<(NCHUNK * NPAIR) / 256, 256>>>(xh);
    // 3) hidden = relu(combined @ W1^T + b1) -> fp16
    gemm_h<1><<<dim3(Hd / 128, M_TOT / 128), 128, DYN_SMEM>>>(
        comb, W1h, b1, hidden, M_TOT, Hd, Id);
    // 4) out = hidden @ W2^T + b2 -> fp32
    gemm_h<0><<<dim3(Od / 128, M_TOT / 128), 128, DYN_SMEM>>>(
        hidden, W2h, b2, d_out, M_TOT, Od, Hd);
}